// round 10
// baseline (speedup 1.0000x reference)
#include <cuda_runtime.h>

// SeparateLoss: mean over the N x N cosine-sim matrix masked by label
// inequality. Binary labels => (2/N^2) * dot(S0, S1),
// Sk = sum of L2-normalized feature rows with label k.
//
// feat [4, 64, 128, 128] f32, label [4, 1, 128, 128] i32.
// Nearest 128->64 picks even indices. N = 16384, C = 64.
//
// 128 blocks x 512 threads, one balanced wave, 2 rows per block.
// Two-level ticket reduction: 8 groups x 16 blocks. Group finisher
// reduces its 16 columns (parallel across 8 SMs); global finisher
// reduces 8 group sums + dot. All combines fixed-order (deterministic).

#define B 4
#define C 64
#define H 128
#define W 128
#define X 64
#define NBLK 128
#define NGRP 8
#define GSZ 16                      // blocks per group
#define NSLOT 128
#define NTOT 16384.0f
#define TP 66                       // T pitch (floats)

__device__ __align__(16) float g_partial[NSLOT * NBLK]; // [slot][blk], fully rewritten
__device__ __align__(16) float g_lvl2[NSLOT * NGRP];    // [slot][grp], fully rewritten
__device__ int g_ticket_grp[NGRP];  // each reset by its group finisher
__device__ int g_ticket;            // reset by global finisher

__global__ void __launch_bounds__(512) separate_fused(
    const float* __restrict__ feat, const int* __restrict__ label,
    float* __restrict__ out)
{
    __shared__ float T[2][C * TP];     // per-row transposed raw values
    __shared__ float sq[2][8 * TP];    // per-row sumsq partials
    __shared__ float invn[2][X];
    __shared__ int   lab[2][X];
    __shared__ float G[2][2 * C];      // [row][class*64+ch]
    __shared__ float S[NSLOT];
    __shared__ int   is_grp_last, is_glob_last;

    const int bx   = blockIdx.x;       // 0..127
    const int grp  = bx >> 4;          // 0..7
    const int tid  = threadIdx.x;      // 0..511
    const int half = tid >> 8;         // row within block
    const int t    = tid & 255;
    const int row  = 2 * bx + half;    // global row 0..255
    const int b    = row >> 6;
    const int yi   = row & 63;
    const int g0   = t >> 5;           // channel-group base 0..7
    const int xj   = t & 31;           // float4 idx: positions 2xj, 2xj+1

    // ---- 8 x LDG.128: channels g0+8k, source row y=2*yi ----
    const float4* fb = reinterpret_cast<const float4*>(
        feat + (((size_t)(b * C + g0) * H) + 2 * yi) * W) + xj;
    float4 v[8];
    #pragma unroll
    for (int k = 0; k < 8; k++)
        v[k] = fb[(size_t)(8 * k) * (H * W / 4)];

    // labels via int4: 32 threads per row, keep .x/.z (even indices)
    if (t < 32) {
        const int4 lv = reinterpret_cast<const int4*>(
            label + b * (H * W) + 2 * yi * W)[t];
        lab[half][2 * t]     = lv.x;
        lab[half][2 * t + 1] = lv.z;
    }

    // ---- sumsq partials in registers (8 channels, 2 positions) ----
    {
        float p0 = 0.f, p1 = 0.f;
        #pragma unroll
        for (int k = 0; k < 8; k++) {
            p0 += v[k].x * v[k].x;     // pos 2xj
            p1 += v[k].z * v[k].z;     // pos 2xj+1
        }
        *reinterpret_cast<float2*>(&sq[half][g0 * TP + 2 * xj]) =
            make_float2(p0, p1);
    }
    // ---- transpose raw values: T[ch][pos] ----
    #pragma unroll
    for (int k = 0; k < 8; k++)
        *reinterpret_cast<float2*>(&T[half][(g0 + 8 * k) * TP + 2 * xj]) =
            make_float2(v[k].x, v[k].z);
    __syncthreads();

    // ---- inverse norms: 2 lanes per position, fixed-order sums ----
    if (t < 2 * X) {
        const int pos = t >> 1;
        const int h   = t & 1;
        const float* q = sq[half] + (4 * h) * TP + pos;
        float s = (q[0 * TP] + q[1 * TP]) + (q[2 * TP] + q[3 * TP]);
        s += __shfl_xor_sync(0xffffffffu, s, 1);
        if (h == 0)
            invn[half][pos] = rsqrtf(fmaxf(s, 1e-24f)); // == 1/max(||f||,1e-12)
    }
    __syncthreads();

    // ---- class sums: ch = t>>2, q = t&3; shfl-combine quarters ----
    {
        const int ch = t >> 2;
        const int q  = t & 3;
        float s0 = 0.f, s1 = 0.f;
        #pragma unroll
        for (int j = 0; j < 16; j++) {
            const int   p = q * 16 + j;
            const float c = T[half][ch * TP + p] * invn[half][p];
            if (lab[half][p] == 0) s0 += c; else s1 += c;
        }
        s0 += __shfl_xor_sync(0xffffffffu, s0, 1);
        s0 += __shfl_xor_sync(0xffffffffu, s0, 2);
        s1 += __shfl_xor_sync(0xffffffffu, s1, 1);
        s1 += __shfl_xor_sync(0xffffffffu, s1, 2);
        if (q == 0) {
            G[half][ch]     = s0;      // class 0
            G[half][C + ch] = s1;      // class 1
        }
    }
    __syncthreads();

    // ---- combine block's two rows (fixed order), write partials ----
    if (tid < NSLOT)
        g_partial[tid * NBLK + bx] = G[0][tid] + G[1][tid];

    // ---- level-1 ticket (release orders this block's partial stores) ----
    if (tid == 0) {
        int tk;
        asm volatile("atom.add.acq_rel.gpu.s32 %0, [%1], 1;"
                     : "=r"(tk) : "l"(&g_ticket_grp[grp]) : "memory");
        is_grp_last = (tk == GSZ - 1);
    }
    __syncthreads();
    if (!is_grp_last) return;
    asm volatile("fence.acq_rel.gpu;" ::: "memory");

    // ---- group reduction: 4 threads/slot, 1 float4 each (16 cols) ----
    {
        const int slot = tid >> 2;     // 0..127
        const int part = tid & 3;
        const float4 u = reinterpret_cast<const float4*>(
            g_partial + slot * NBLK + grp * GSZ)[part];
        float acc = (u.x + u.y) + (u.z + u.w);
        acc += __shfl_xor_sync(0xffffffffu, acc, 1);
        acc += __shfl_xor_sync(0xffffffffu, acc, 2);
        if (part == 0)
            g_lvl2[slot * NGRP + grp] = acc;
    }
    if (tid == 0) g_ticket_grp[grp] = 0;   // rearm (all group members arrived)

    // ---- level-2 ticket ----
    if (tid == 0) {
        int tk;
        asm volatile("atom.add.acq_rel.gpu.s32 %0, [%1], 1;"
                     : "=r"(tk) : "l"(&g_ticket) : "memory");
        is_glob_last = (tk == NGRP - 1);
    }
    __syncthreads();
    if (!is_glob_last) return;
    asm volatile("fence.acq_rel.gpu;" ::: "memory");

    // ---- final: 2 threads/slot, 1 float4 each (8 group sums) ----
    if (tid < 256) {
        const int slot = tid >> 1;
        const int part = tid & 1;
        const float4 u = reinterpret_cast<const float4*>(
            g_lvl2 + slot * NGRP)[part];
        float acc = (u.x + u.y) + (u.z + u.w);
        acc += __shfl_xor_sync(0xffffffffu, acc, 1);
        if (part == 0) S[slot] = acc;
    }
    __syncthreads();

    if (tid < 32) {
        float d = S[tid] * S[C + tid] + S[tid + 32] * S[C + tid + 32];
        #pragma unroll
        for (int o = 16; o > 0; o >>= 1)
            d += __shfl_down_sync(0xffffffffu, d, o);
        if (tid == 0) {
            out[0] = d * (2.0f / (NTOT * NTOT));
            g_ticket = 0;              // rearm for next replay
        }
    }
}

extern "C" void kernel_launch(void* const* d_in, const int* in_sizes, int n_in,
                              void* d_out, int out_size)
{
    const float* feat  = (const float*)d_in[0];
    const int*   label = (const int*)d_in[1];
    float*       out   = (float*)d_out;

    (void)in_sizes; (void)n_in; (void)out_size;

    separate_fused<<<NBLK, 512>>>(feat, label, out);
}

// round 11
// speedup vs baseline: 1.1940x; 1.1940x over previous
#include <cuda_runtime.h>

// SeparateLoss: mean over the N x N cosine-sim matrix masked by label
// inequality. Binary labels => (2/N^2) * dot(S0, S1),
// Sk = sum of L2-normalized feature rows with label k.
//
// feat [4, 64, 128, 128] f32, label [4, 1, 128, 128] i32.
// Nearest 128->64 picks even indices. N = 16384, C = 64.
//
// R9 structure (best): 128 blocks x 512 threads = one balanced wave,
// 2 output rows per block, 8 x LDG.128 front-batched per thread, sumsq in
// registers, float2 smem transpose, shfl class-combine, rows combined
// in-block. Single-level acq_rel ticket; last block reduces 64KB of
// partials in fixed order (bitwise-deterministic).
// Only change vs R9: label loads via int4 (fewer LSU issues).

#define B 4
#define C 64
#define H 128
#define W 128
#define X 64
#define NBLK 128
#define NSLOT 128
#define NTOT 16384.0f
#define TP 66                       // T pitch (floats)

__device__ __align__(16) float g_partial[NSLOT * NBLK];  // [slot][blk], fully rewritten
__device__ int g_ticket = 0;

__global__ void __launch_bounds__(512) separate_fused(
    const float* __restrict__ feat, const int* __restrict__ label,
    float* __restrict__ out)
{
    __shared__ float T[2][C * TP];     // per-row transposed raw values
    __shared__ float sq[2][8 * TP];    // per-row sumsq partials
    __shared__ float invn[2][X];
    __shared__ int   lab[2][X];
    __shared__ float G[2][2 * C];      // [row][class*64+ch]
    __shared__ float S[NSLOT];
    __shared__ int   is_last;

    const int bx   = blockIdx.x;       // 0..127
    const int tid  = threadIdx.x;      // 0..511
    const int half = tid >> 8;         // row within block
    const int t    = tid & 255;
    const int row  = 2 * bx + half;    // global row 0..255
    const int b    = row >> 6;
    const int yi   = row & 63;
    const int g0   = t >> 5;           // channel-group base 0..7
    const int xj   = t & 31;           // float4 idx: positions 2xj, 2xj+1

    // ---- 8 x LDG.128: channels g0+8k, source row y=2*yi ----
    const float4* fb = reinterpret_cast<const float4*>(
        feat + (((size_t)(b * C + g0) * H) + 2 * yi) * W) + xj;
    float4 v[8];
    #pragma unroll
    for (int k = 0; k < 8; k++)
        v[k] = fb[(size_t)(8 * k) * (H * W / 4)];

    // labels via int4: 32 threads per row, keep .x/.z (even indices)
    if (t < 32) {
        const int4 lv = reinterpret_cast<const int4*>(
            label + b * (H * W) + 2 * yi * W)[t];
        lab[half][2 * t]     = lv.x;
        lab[half][2 * t + 1] = lv.z;
    }

    // ---- sumsq partials in registers (8 channels, 2 positions) ----
    {
        float p0 = 0.f, p1 = 0.f;
        #pragma unroll
        for (int k = 0; k < 8; k++) {
            p0 += v[k].x * v[k].x;     // pos 2xj
            p1 += v[k].z * v[k].z;     // pos 2xj+1
        }
        *reinterpret_cast<float2*>(&sq[half][g0 * TP + 2 * xj]) =
            make_float2(p0, p1);
    }
    // ---- transpose raw values: T[ch][pos] ----
    #pragma unroll
    for (int k = 0; k < 8; k++)
        *reinterpret_cast<float2*>(&T[half][(g0 + 8 * k) * TP + 2 * xj]) =
            make_float2(v[k].x, v[k].z);
    __syncthreads();

    // ---- inverse norms: 2 lanes per position, fixed-order sums ----
    if (t < 2 * X) {
        const int pos = t >> 1;
        const int h   = t & 1;         // chgroups 0-3 vs 4-7
        const float* q = sq[half] + (4 * h) * TP + pos;
        float s = (q[0 * TP] + q[1 * TP]) + (q[2 * TP] + q[3 * TP]);
        s += __shfl_xor_sync(0xffffffffu, s, 1);
        if (h == 0)
            invn[half][pos] = rsqrtf(fmaxf(s, 1e-24f));  // == 1/max(||f||,1e-12)
    }
    __syncthreads();

    // ---- class sums: ch = t>>2, q = t&3; shfl-combine quarters ----
    {
        const int ch = t >> 2;
        const int q  = t & 3;
        float s0 = 0.f, s1 = 0.f;
        #pragma unroll
        for (int j = 0; j < 16; j++) {
            const int   p = q * 16 + j;
            const float c = T[half][ch * TP + p] * invn[half][p];
            if (lab[half][p] == 0) s0 += c; else s1 += c;
        }
        s0 += __shfl_xor_sync(0xffffffffu, s0, 1);
        s0 += __shfl_xor_sync(0xffffffffu, s0, 2);
        s1 += __shfl_xor_sync(0xffffffffu, s1, 1);
        s1 += __shfl_xor_sync(0xffffffffu, s1, 2);
        if (q == 0) {
            G[half][ch]     = s0;      // class 0
            G[half][C + ch] = s1;      // class 1
        }
    }
    __syncthreads();

    // ---- combine the block's two rows (fixed order), write partials ----
    if (tid < NSLOT)
        g_partial[tid * NBLK + bx] = G[0][tid] + G[1][tid];

    // ---- ticket: release-RMW orders the partial stores (no membar) ----
    if (tid == 0) {
        int tk;
        asm volatile("atom.add.acq_rel.gpu.s32 %0, [%1], 1;"
                     : "=r"(tk) : "l"(&g_ticket) : "memory");
        is_last = (tk == NBLK - 1);
    }
    __syncthreads();
    if (!is_last) return;
    asm volatile("fence.acq_rel.gpu;" ::: "memory");   // propagate acquire to block

    // ---- deterministic final reduction: 4 threads/slot, 8 float4 each ----
    {
        const int slot = tid >> 2;     // 0..127
        const int part = tid & 3;
        const float4* p =
            reinterpret_cast<const float4*>(g_partial + slot * NBLK) + part * 8;
        float acc = 0.f;
        #pragma unroll
        for (int i = 0; i < 8; i++) {
            const float4 u = p[i];
            acc += (u.x + u.y) + (u.z + u.w);
        }
        acc += __shfl_xor_sync(0xffffffffu, acc, 1);
        acc += __shfl_xor_sync(0xffffffffu, acc, 2);
        if (part == 0) S[slot] = acc;
    }
    __syncthreads();

    if (tid < 32) {
        float d = S[tid] * S[C + tid] + S[tid + 32] * S[C + tid + 32];
        #pragma unroll
        for (int o = 16; o > 0; o >>= 1)
            d += __shfl_down_sync(0xffffffffu, d, o);
        if (tid == 0) {
            out[0] = d * (2.0f / (NTOT * NTOT));
            g_ticket = 0;              // rearm for next replay
        }
    }
}

extern "C" void kernel_launch(void* const* d_in, const int* in_sizes, int n_in,
                              void* d_out, int out_size)
{
    const float* feat  = (const float*)d_in[0];
    const int*   label = (const int*)d_in[1];
    float*       out   = (float*)d_out;

    (void)in_sizes; (void)n_in; (void)out_size;

    separate_fused<<<NBLK, 512>>>(feat, label, out);
}